// round 6
// baseline (speedup 1.0000x reference)
#include <cuda_runtime.h>
#include <cuda_bf16.h>
#include <cstdint>
#include <cstddef>
#include <mma.h>

using namespace nvcuda;

#define B_ 8
#define S_ 2048
#define E_ 1024

// ================= scratch (device globals; allocation-free rule) =================
__device__ __nv_bfloat16 g_Qhi[(size_t)B_ * S_ * E_];
__device__ __nv_bfloat16 g_Qlo[(size_t)B_ * S_ * E_];
__device__ __nv_bfloat16 g_Khi[(size_t)B_ * S_ * E_];
__device__ __nv_bfloat16 g_Klo[(size_t)B_ * S_ * E_];
__device__ __nv_bfloat16 g_Vthi[(size_t)B_ * E_ * S_];  // V transposed: [B, E, S]
__device__ __nv_bfloat16 g_Vtlo[(size_t)B_ * E_ * S_];
__device__ __nv_bfloat16 g_Whi[(size_t)E_ * E_];
__device__ __nv_bfloat16 g_Wlo[(size_t)E_ * E_];
__device__ float         g_scores[(size_t)B_ * S_ * S_];
__device__ __nv_bfloat16 g_Phi[(size_t)B_ * S_ * S_];
__device__ __nv_bfloat16 g_Plo[(size_t)B_ * S_ * S_];
// attn split reuses g_Qhi/g_Qlo (Q dead after GEMM1)

// ================= async-copy helpers =================
__device__ __forceinline__ uint32_t smem_u32(const void* p) {
    uint32_t a;
    asm("{ .reg .u64 t; cvta.to.shared.u64 t, %1; cvt.u32.u64 %0, t; }" : "=r"(a) : "l"(p));
    return a;
}
__device__ __forceinline__ void cp16(uint32_t dst, const void* src) {
    asm volatile("cp.async.cg.shared.global [%0], [%1], 16;" :: "r"(dst), "l"(src) : "memory");
}
__device__ __forceinline__ void cp_commit() { asm volatile("cp.async.commit_group;" ::: "memory"); }
__device__ __forceinline__ void cp_wait1()  { asm volatile("cp.async.wait_group 1;" ::: "memory"); }

// ================= split kernels =================
__global__ void __launch_bounds__(256) split_plane(const float* __restrict__ x,
                                                   __nv_bfloat16* __restrict__ hi,
                                                   __nv_bfloat16* __restrict__ lo, int n8) {
    int i = blockIdx.x * blockDim.x + threadIdx.x;
    if (i >= n8) return;
    const float4* x4 = reinterpret_cast<const float4*>(x) + (size_t)i * 2;
    float4 a = x4[0], b = x4[1];
    float f[8] = {a.x, a.y, a.z, a.w, b.x, b.y, b.z, b.w};
    __nv_bfloat16 h[8], l[8];
#pragma unroll
    for (int j = 0; j < 8; j++) {
        h[j] = __float2bfloat16(f[j]);
        l[j] = __float2bfloat16(f[j] - __bfloat162float(h[j]));
    }
    *reinterpret_cast<uint4*>(hi + (size_t)i * 8) = *reinterpret_cast<const uint4*>(h);
    *reinterpret_cast<uint4*>(lo + (size_t)i * 8) = *reinterpret_cast<const uint4*>(l);
}

// V [B,S,E] f32 -> transposed planes [B,E,S] bf16 hi/lo
__global__ void __launch_bounds__(256) splitT_v(const float* __restrict__ v,
                                                __nv_bfloat16* __restrict__ hi,
                                                __nv_bfloat16* __restrict__ lo) {
    __shared__ float tile[32][33];
    int b = blockIdx.z;
    int s0 = blockIdx.x * 32, e0 = blockIdx.y * 32;
    int tx = threadIdx.x & 31, ty = threadIdx.x >> 5;
    const float* vb = v + (size_t)b * S_ * E_;
#pragma unroll
    for (int k = 0; k < 4; k++)
        tile[ty + 8 * k][tx] = vb[(size_t)(s0 + ty + 8 * k) * E_ + e0 + tx];
    __syncthreads();
    __nv_bfloat16* hb = hi + (size_t)b * E_ * S_;
    __nv_bfloat16* lb = lo + (size_t)b * E_ * S_;
#pragma unroll
    for (int k = 0; k < 4; k++) {
        float f = tile[tx][ty + 8 * k];
        __nv_bfloat16 h = __float2bfloat16(f);
        size_t o = (size_t)(e0 + ty + 8 * k) * S_ + s0 + tx;
        hb[o] = h;
        lb[o] = __float2bfloat16(f - __bfloat162float(h));
    }
}

// ================= softmax * mask -> planar bf16 hi/lo probs =================
__global__ void __launch_bounds__(256) softmax_mask_kernel(
    const float* __restrict__ scores, const float* __restrict__ mask,
    __nv_bfloat16* __restrict__ phi, __nv_bfloat16* __restrict__ plo,
    const int* __restrict__ sc) {
    __shared__ float redmax[8], redsum[8];
    size_t row = blockIdx.x;
    const float* srow = scores + row * (size_t)S_;
    const float* mrow = mask + row * (size_t)S_;
    int t = threadIdx.x, lane = t & 31, warp = t >> 5;

    int iv = *sc;
    float denom = (iv == 32) ? 32.0f : __int_as_float(iv);
    float scale = 1.0f / denom;

    float v[8];
#pragma unroll
    for (int j = 0; j < 8; j++) v[j] = srow[t + 256 * j] * scale;
    float m = v[0];
#pragma unroll
    for (int j = 1; j < 8; j++) m = fmaxf(m, v[j]);
#pragma unroll
    for (int o = 16; o; o >>= 1) m = fmaxf(m, __shfl_xor_sync(0xffffffffu, m, o));
    if (lane == 0) redmax[warp] = m;
    __syncthreads();
    float bm = redmax[0];
#pragma unroll
    for (int w = 1; w < 8; w++) bm = fmaxf(bm, redmax[w]);
    float e[8], s = 0.f;
#pragma unroll
    for (int j = 0; j < 8; j++) { e[j] = __expf(v[j] - bm); s += e[j]; }
#pragma unroll
    for (int o = 16; o; o >>= 1) s += __shfl_xor_sync(0xffffffffu, s, o);
    if (lane == 0) redsum[warp] = s;
    __syncthreads();
    float bs = 0.f;
#pragma unroll
    for (int w = 0; w < 8; w++) bs += redsum[w];
    float inv = 1.0f / bs;

    __nv_bfloat16* ph = phi + row * (size_t)S_;
    __nv_bfloat16* pl = plo + row * (size_t)S_;
#pragma unroll
    for (int j = 0; j < 8; j++) {
        float p = e[j] * inv * mrow[t + 256 * j];
        __nv_bfloat16 h = __float2bfloat16(p);
        ph[t + 256 * j] = h;
        pl[t + 256 * j] = __float2bfloat16(p - __bfloat162float(h));
    }
}

// ================= pipelined split-bf16 WMMA NT GEMM (64x64 warp tiles) ========
// C[M,N] = sum_k A[m,k]*B[n,k]; A/B planar hi/lo bf16, fp32 accum via HMMA.
// Block tile 256(M) x 128(N) x 32(K); 8 warps as 4x2 grid of 64x64 warp tiles.
// MODE 0: f32 out. MODE 1: planar bf16 hi/lo out. MODE 2: f32 + bias out.
constexpr int BM = 256, BN = 128, BK = 32;
constexpr int PITCH = 40;                       // BK + 8 pad (bf16 elems) = 80 B/row
constexpr int PLA = BM * PITCH * 2;             // A plane tile bytes = 20480
constexpr int PLB = BN * PITCH * 2;             // B plane tile bytes = 10240
constexpr int STAGEB = 2 * PLA + 2 * PLB;       // 61440 B
constexpr int STAGES = 3;
constexpr unsigned GSMEM = STAGES * STAGEB;     // 184320 B

template <int MODE>
__global__ void __launch_bounds__(256, 1) gemm_pipe(
    const __nv_bfloat16* __restrict__ Ahi, const __nv_bfloat16* __restrict__ Alo,
    int lda, size_t strA,
    const __nv_bfloat16* __restrict__ Bhi, const __nv_bfloat16* __restrict__ Blo,
    int ldb, size_t strB,
    void* __restrict__ C0, void* __restrict__ C1, int ldc, size_t strC,
    const float* __restrict__ bias, int Kdim) {
    extern __shared__ __nv_bfloat16 smem[];
    const uint32_t sbase = smem_u32(smem);
    const int tid = threadIdx.x;
    const int lane = tid & 31, wid = tid >> 5;
    const int wm = wid >> 1;                 // 0..3  (64-row strips)
    const int wn = wid & 1;                  // 0..1  (64-col strips)
    const int b = blockIdx.z;
    const int m0 = blockIdx.y * BM, n0 = blockIdx.x * BN;

    const __nv_bfloat16* pa[2] = {Ahi + (size_t)b * strA, Alo + (size_t)b * strA};
    const __nv_bfloat16* pb[2] = {Bhi + (size_t)b * strB, Blo + (size_t)b * strB};

    const int niter = Kdim / BK;

    // stage loader: A planes 256x32, B planes 128x32, cp.async 16B chunks (4/row)
    auto load_stage = [&](int j) {
        const int k0 = j * BK;
        const uint32_t sb = sbase + (j % STAGES) * STAGEB;
#pragma unroll
        for (int p = 0; p < 2; p++) {
#pragma unroll
            for (int it = 0; it < 4; it++) {
                int id = tid + it * 256;                 // 1024 chunks
                int r = id >> 2, c = id & 3;             // 256 rows x 4 chunks
                uint32_t dst = sb + (uint32_t)p * PLA + (uint32_t)(r * (PITCH * 2) + c * 16);
                cp16(dst, pa[p] + (size_t)(m0 + r) * lda + k0 + c * 8);
            }
        }
#pragma unroll
        for (int p = 0; p < 2; p++) {
#pragma unroll
            for (int it = 0; it < 2; it++) {
                int id = tid + it * 256;                 // 512 chunks
                int r = id >> 2, c = id & 3;             // 128 rows x 4 chunks
                uint32_t dst = sb + (uint32_t)(2 * PLA) + (uint32_t)p * PLB +
                               (uint32_t)(r * (PITCH * 2) + c * 16);
                cp16(dst, pb[p] + (size_t)(n0 + r) * ldb + k0 + c * 8);
            }
        }
    };

    wmma::fragment<wmma::accumulator, 16, 16, 16, float> acc[4][4];
#pragma unroll
    for (int i = 0; i < 4; i++)
#pragma unroll
        for (int j = 0; j < 4; j++) wmma::fill_fragment(acc[i][j], 0.f);

    // prologue
    load_stage(0); cp_commit();
    load_stage(1); cp_commit();

    for (int i = 0; i < niter; i++) {
        cp_wait1();          // stage i resident (only stage i+1 may still be in flight)
        __syncthreads();

        // prefetch stage i+2 (overwrites buffer of stage i-1; safe past the barrier)
        if (i + 2 < niter) load_stage(i + 2);
        cp_commit();

        // compute stage i
        const __nv_bfloat16* As_hi = smem + (size_t)(i % STAGES) * (STAGEB / 2);
        const __nv_bfloat16* As_lo = As_hi + PLA / 2;
        const __nv_bfloat16* Bs_hi = As_hi + PLA;          // 2*PLA/2
        const __nv_bfloat16* Bs_lo = Bs_hi + PLB / 2;

#pragma unroll
        for (int kk = 0; kk < BK; kk += 16) {
            wmma::fragment<wmma::matrix_a, 16, 16, 16, __nv_bfloat16, wmma::row_major> ah[4], al[4];
#pragma unroll
            for (int x = 0; x < 4; x++) {
                int row = wm * 64 + x * 16;
                wmma::load_matrix_sync(ah[x], As_hi + row * PITCH + kk, PITCH);
                wmma::load_matrix_sync(al[x], As_lo + row * PITCH + kk, PITCH);
            }
#pragma unroll
            for (int y = 0; y < 4; y++) {
                int col = wn * 64 + y * 16;
                wmma::fragment<wmma::matrix_b, 16, 16, 16, __nv_bfloat16, wmma::col_major> bh, bl;
                wmma::load_matrix_sync(bh, Bs_hi + col * PITCH + kk, PITCH);
                wmma::load_matrix_sync(bl, Bs_lo + col * PITCH + kk, PITCH);
#pragma unroll
                for (int x = 0; x < 4; x++) {
                    wmma::mma_sync(acc[x][y], ah[x], bh, acc[x][y]);
                    wmma::mma_sync(acc[x][y], ah[x], bl, acc[x][y]);
                    wmma::mma_sync(acc[x][y], al[x], bh, acc[x][y]);
                }
            }
        }
        __syncthreads();
    }

    // ---------------- epilogue ----------------
    if (MODE == 0) {
        float* C = reinterpret_cast<float*>(C0) + (size_t)b * strC;
#pragma unroll
        for (int x = 0; x < 4; x++)
#pragma unroll
            for (int y = 0; y < 4; y++) {
                int gr = m0 + wm * 64 + x * 16;
                int gc = n0 + wn * 64 + y * 16;
                wmma::store_matrix_sync(C + (size_t)gr * ldc + gc, acc[x][y], ldc,
                                        wmma::mem_row_major);
            }
    } else {
        // per-warp 16x72 f32 staging slab (stage buffers dead after final barrier)
        float* stage = reinterpret_cast<float*>(smem) + wid * (16 * 72);
        int wr0 = m0 + wm * 64, wc0 = n0 + wn * 64;
#pragma unroll
        for (int x = 0; x < 4; x++) {
#pragma unroll
            for (int y = 0; y < 4; y++)
                wmma::store_matrix_sync(stage + y * 16, acc[x][y], 72, wmma::mem_row_major);
            __syncwarp();
#pragma unroll
            for (int it = 0; it < 8; it++) {
                int idx = lane + it * 32;
                int r = idx >> 4, c = (idx & 15) << 2;
                float4 v = *reinterpret_cast<float4*>(stage + r * 72 + c);
                int gr = wr0 + x * 16 + r, gc = wc0 + c;
                if (MODE == 2) {
                    v.x += bias[gc]; v.y += bias[gc + 1];
                    v.z += bias[gc + 2]; v.w += bias[gc + 3];
                    float* C = reinterpret_cast<float*>(C0);
                    *reinterpret_cast<float4*>(C + (size_t)gr * ldc + gc) = v;
                } else {
                    __nv_bfloat16* Ch = reinterpret_cast<__nv_bfloat16*>(C0) + (size_t)b * strC;
                    __nv_bfloat16* Cl = reinterpret_cast<__nv_bfloat16*>(C1) + (size_t)b * strC;
                    float f[4] = {v.x, v.y, v.z, v.w};
                    __nv_bfloat16 h[4], l[4];
#pragma unroll
                    for (int q = 0; q < 4; q++) {
                        h[q] = __float2bfloat16(f[q]);
                        l[q] = __float2bfloat16(f[q] - __bfloat162float(h[q]));
                    }
                    size_t o = (size_t)gr * ldc + gc;
                    *reinterpret_cast<uint2*>(Ch + o) = *reinterpret_cast<const uint2*>(h);
                    *reinterpret_cast<uint2*>(Cl + o) = *reinterpret_cast<const uint2*>(l);
                }
            }
            __syncwarp();
        }
    }
}

// ================= launch =================
extern "C" void kernel_launch(void* const* d_in, const int* in_sizes, int n_in,
                              void* d_out, int out_size) {
    const float* Q    = (const float*)d_in[0];
    const float* Kx   = (const float*)d_in[1];
    const float* V    = (const float*)d_in[2];
    const float* mask = (const float*)d_in[3];
    const float* W    = (const float*)d_in[4];
    const float* bias = (const float*)d_in[5];
    const int*   inv  = (const int*)d_in[6];

    void *pQh, *pQl, *pKh, *pKl, *pVh, *pVl, *pWh, *pWl, *pS, *pPh, *pPl;
    cudaGetSymbolAddress(&pQh, g_Qhi);  cudaGetSymbolAddress(&pQl, g_Qlo);
    cudaGetSymbolAddress(&pKh, g_Khi);  cudaGetSymbolAddress(&pKl, g_Klo);
    cudaGetSymbolAddress(&pVh, g_Vthi); cudaGetSymbolAddress(&pVl, g_Vtlo);
    cudaGetSymbolAddress(&pWh, g_Whi);  cudaGetSymbolAddress(&pWl, g_Wlo);
    cudaGetSymbolAddress(&pS, g_scores);
    cudaGetSymbolAddress(&pPh, g_Phi);  cudaGetSymbolAddress(&pPl, g_Plo);

    __nv_bfloat16 *Qh = (__nv_bfloat16*)pQh, *Ql = (__nv_bfloat16*)pQl;
    __nv_bfloat16 *Kh = (__nv_bfloat16*)pKh, *Kl = (__nv_bfloat16*)pKl;
    __nv_bfloat16 *Vh = (__nv_bfloat16*)pVh, *Vl = (__nv_bfloat16*)pVl;
    __nv_bfloat16 *Wh = (__nv_bfloat16*)pWh, *Wl = (__nv_bfloat16*)pWl;
    float* Sc = (float*)pS;
    __nv_bfloat16 *Ph = (__nv_bfloat16*)pPh, *Pl = (__nv_bfloat16*)pPl;
    __nv_bfloat16 *Ath = Qh, *Atl = Ql;  // attn reuses Q planes

    cudaFuncSetAttribute(gemm_pipe<0>, cudaFuncAttributeMaxDynamicSharedMemorySize, GSMEM);
    cudaFuncSetAttribute(gemm_pipe<1>, cudaFuncAttributeMaxDynamicSharedMemorySize, GSMEM);
    cudaFuncSetAttribute(gemm_pipe<2>, cudaFuncAttributeMaxDynamicSharedMemorySize, GSMEM);

    // splits
    int n8 = B_ * S_ * E_ / 8;
    split_plane<<<(n8 + 255) / 256, 256>>>(Q, Qh, Ql, n8);
    split_plane<<<(n8 + 255) / 256, 256>>>(Kx, Kh, Kl, n8);
    int w8 = E_ * E_ / 8;
    split_plane<<<(w8 + 255) / 256, 256>>>(W, Wh, Wl, w8);
    dim3 gt(S_ / 32, E_ / 32, B_);
    splitT_v<<<gt, 256>>>(V, Vh, Vl);

    // GEMM1: scores = Q @ K^T  [M=S, N=S, K=E]
    dim3 g1(S_ / BN, S_ / BM, B_);
    gemm_pipe<0><<<g1, 256, GSMEM>>>(Qh, Ql, E_, (size_t)S_ * E_,
                                     Kh, Kl, E_, (size_t)S_ * E_,
                                     Sc, nullptr, S_, (size_t)S_ * S_, nullptr, E_);

    // softmax * mask -> planar probs
    softmax_mask_kernel<<<B_ * S_, 256>>>(Sc, mask, Ph, Pl, inv);

    // GEMM2: attn = P @ Vt^T   [M=S, N=E, K=S]
    dim3 g2(E_ / BN, S_ / BM, B_);
    gemm_pipe<1><<<g2, 256, GSMEM>>>(Ph, Pl, S_, (size_t)S_ * S_,
                                     Vh, Vl, S_, (size_t)E_ * S_,
                                     Ath, Atl, E_, (size_t)S_ * E_, nullptr, S_);

    // GEMM3: out = attn @ W^T + bias  [M=B*S, N=E, K=E]
    dim3 g3(E_ / BN, (B_ * S_) / BM, 1);
    gemm_pipe<2><<<g3, 256, GSMEM>>>(Ath, Atl, E_, 0,
                                     Wh, Wl, E_, 0,
                                     d_out, nullptr, E_, 0, bias, E_);
}

// round 7
// speedup vs baseline: 1.0186x; 1.0186x over previous
#include <cuda_runtime.h>
#include <cuda_bf16.h>
#include <cstdint>
#include <cstddef>
#include <mma.h>

using namespace nvcuda;

#define B_ 8
#define S_ 2048
#define E_ 1024

// ================= scratch (device globals; allocation-free rule) =================
__device__ __nv_bfloat16 g_Qhi[(size_t)B_ * S_ * E_];
__device__ __nv_bfloat16 g_Qlo[(size_t)B_ * S_ * E_];
__device__ __nv_bfloat16 g_Khi[(size_t)B_ * S_ * E_];
__device__ __nv_bfloat16 g_Klo[(size_t)B_ * S_ * E_];
__device__ __nv_bfloat16 g_Vthi[(size_t)B_ * E_ * S_];  // V transposed: [B, E, S]
__device__ __nv_bfloat16 g_Vtlo[(size_t)B_ * E_ * S_];
__device__ __nv_bfloat16 g_Whi[(size_t)E_ * E_];
__device__ __nv_bfloat16 g_Wlo[(size_t)E_ * E_];
__device__ float         g_scores[(size_t)B_ * S_ * S_];
__device__ __nv_bfloat16 g_Phi[(size_t)B_ * S_ * S_];
__device__ __nv_bfloat16 g_Plo[(size_t)B_ * S_ * S_];
// attn split reuses g_Qhi/g_Qlo (Q dead after GEMM1)

// ================= async-copy helpers =================
__device__ __forceinline__ uint32_t smem_u32(const void* p) {
    uint32_t a;
    asm("{ .reg .u64 t; cvta.to.shared.u64 t, %1; cvt.u32.u64 %0, t; }" : "=r"(a) : "l"(p));
    return a;
}
__device__ __forceinline__ void cp16(uint32_t dst, const void* src) {
    asm volatile("cp.async.cg.shared.global [%0], [%1], 16;" :: "r"(dst), "l"(src) : "memory");
}
__device__ __forceinline__ void cp_commit() { asm volatile("cp.async.commit_group;" ::: "memory"); }
__device__ __forceinline__ void cp_wait1()  { asm volatile("cp.async.wait_group 1;" ::: "memory"); }

// ================= split kernels =================
__global__ void __launch_bounds__(256) split_plane(const float* __restrict__ x,
                                                   __nv_bfloat16* __restrict__ hi,
                                                   __nv_bfloat16* __restrict__ lo, int n8) {
    int i = blockIdx.x * blockDim.x + threadIdx.x;
    if (i >= n8) return;
    const float4* x4 = reinterpret_cast<const float4*>(x) + (size_t)i * 2;
    float4 a = x4[0], b = x4[1];
    float f[8] = {a.x, a.y, a.z, a.w, b.x, b.y, b.z, b.w};
    __nv_bfloat16 h[8], l[8];
#pragma unroll
    for (int j = 0; j < 8; j++) {
        h[j] = __float2bfloat16(f[j]);
        l[j] = __float2bfloat16(f[j] - __bfloat162float(h[j]));
    }
    *reinterpret_cast<uint4*>(hi + (size_t)i * 8) = *reinterpret_cast<const uint4*>(h);
    *reinterpret_cast<uint4*>(lo + (size_t)i * 8) = *reinterpret_cast<const uint4*>(l);
}

// V [B,S,E] f32 -> transposed planes [B,E,S] bf16 hi/lo
__global__ void __launch_bounds__(256) splitT_v(const float* __restrict__ v,
                                                __nv_bfloat16* __restrict__ hi,
                                                __nv_bfloat16* __restrict__ lo) {
    __shared__ float tile[32][33];
    int b = blockIdx.z;
    int s0 = blockIdx.x * 32, e0 = blockIdx.y * 32;
    int tx = threadIdx.x & 31, ty = threadIdx.x >> 5;
    const float* vb = v + (size_t)b * S_ * E_;
#pragma unroll
    for (int k = 0; k < 4; k++)
        tile[ty + 8 * k][tx] = vb[(size_t)(s0 + ty + 8 * k) * E_ + e0 + tx];
    __syncthreads();
    __nv_bfloat16* hb = hi + (size_t)b * E_ * S_;
    __nv_bfloat16* lb = lo + (size_t)b * E_ * S_;
#pragma unroll
    for (int k = 0; k < 4; k++) {
        float f = tile[tx][ty + 8 * k];
        __nv_bfloat16 h = __float2bfloat16(f);
        size_t o = (size_t)(e0 + ty + 8 * k) * S_ + s0 + tx;
        hb[o] = h;
        lb[o] = __float2bfloat16(f - __bfloat162float(h));
    }
}

// ================= softmax * mask -> planar bf16 hi/lo probs =================
__global__ void __launch_bounds__(256) softmax_mask_kernel(
    const float* __restrict__ scores, const float* __restrict__ mask,
    __nv_bfloat16* __restrict__ phi, __nv_bfloat16* __restrict__ plo,
    const int* __restrict__ sc) {
    __shared__ float redmax[8], redsum[8];
    size_t row = blockIdx.x;
    const float* srow = scores + row * (size_t)S_;
    const float* mrow = mask + row * (size_t)S_;
    int t = threadIdx.x, lane = t & 31, warp = t >> 5;

    int iv = *sc;
    float denom = (iv == 32) ? 32.0f : __int_as_float(iv);
    float scale = 1.0f / denom;

    float v[8];
#pragma unroll
    for (int j = 0; j < 8; j++) v[j] = srow[t + 256 * j] * scale;
    float m = v[0];
#pragma unroll
    for (int j = 1; j < 8; j++) m = fmaxf(m, v[j]);
#pragma unroll
    for (int o = 16; o; o >>= 1) m = fmaxf(m, __shfl_xor_sync(0xffffffffu, m, o));
    if (lane == 0) redmax[warp] = m;
    __syncthreads();
    float bm = redmax[0];
#pragma unroll
    for (int w = 1; w < 8; w++) bm = fmaxf(bm, redmax[w]);
    float e[8], s = 0.f;
#pragma unroll
    for (int j = 0; j < 8; j++) { e[j] = __expf(v[j] - bm); s += e[j]; }
#pragma unroll
    for (int o = 16; o; o >>= 1) s += __shfl_xor_sync(0xffffffffu, s, o);
    if (lane == 0) redsum[warp] = s;
    __syncthreads();
    float bs = 0.f;
#pragma unroll
    for (int w = 0; w < 8; w++) bs += redsum[w];
    float inv = 1.0f / bs;

    __nv_bfloat16* ph = phi + row * (size_t)S_;
    __nv_bfloat16* pl = plo + row * (size_t)S_;
#pragma unroll
    for (int j = 0; j < 8; j++) {
        float p = e[j] * inv * mrow[t + 256 * j];
        __nv_bfloat16 h = __float2bfloat16(p);
        ph[t + 256 * j] = h;
        pl[t + 256 * j] = __float2bfloat16(p - __bfloat162float(h));
    }
}

// ================= pipelined split-bf16 WMMA NT GEMM =================
// Block tile 256(M) x 128(N) x 64(K); 512 threads; 16 warps as 4x4 grid of
// 64x32 warp tiles; 2-stage cp.async pipeline.
// MODE 0: f32 out. MODE 1: planar bf16 hi/lo out. MODE 2: f32 + bias out.
constexpr int BM = 256, BN = 128, BK = 64;
constexpr int NT = 512;
constexpr int PITCH = 72;                       // BK + 8 pad (bf16 elems) = 144 B/row
constexpr int PLA = BM * PITCH * 2;             // A plane tile bytes = 36864
constexpr int PLB = BN * PITCH * 2;             // B plane tile bytes = 18432
constexpr int STAGEB = 2 * PLA + 2 * PLB;       // 110592 B
constexpr int STAGES = 2;
constexpr unsigned GSMEM = STAGES * STAGEB;     // 221184 B

template <int MODE>
__global__ void __launch_bounds__(NT, 1) gemm_pipe(
    const __nv_bfloat16* __restrict__ Ahi, const __nv_bfloat16* __restrict__ Alo,
    int lda, size_t strA,
    const __nv_bfloat16* __restrict__ Bhi, const __nv_bfloat16* __restrict__ Blo,
    int ldb, size_t strB,
    void* __restrict__ C0, void* __restrict__ C1, int ldc, size_t strC,
    const float* __restrict__ bias, int Kdim) {
    extern __shared__ __nv_bfloat16 smem[];
    const uint32_t sbase = smem_u32(smem);
    const int tid = threadIdx.x;
    const int lane = tid & 31, wid = tid >> 5;
    const int wm = wid >> 2;                 // 0..3  (64-row strips)
    const int wn = wid & 3;                  // 0..3  (32-col strips)
    const int b = blockIdx.z;
    const int m0 = blockIdx.y * BM, n0 = blockIdx.x * BN;

    const __nv_bfloat16* pa[2] = {Ahi + (size_t)b * strA, Alo + (size_t)b * strA};
    const __nv_bfloat16* pb[2] = {Bhi + (size_t)b * strB, Blo + (size_t)b * strB};

    const int niter = Kdim / BK;

    // stage loader: A planes 256x64, B planes 128x64; 16B cp.async chunks (8/row)
    auto load_stage = [&](int j) {
        const int k0 = j * BK;
        const uint32_t sb = sbase + (j % STAGES) * STAGEB;
#pragma unroll
        for (int p = 0; p < 2; p++) {
#pragma unroll
            for (int it = 0; it < 4; it++) {
                int id = tid + it * NT;                  // 2048 chunks
                int r = id >> 3, c = id & 7;             // 256 rows x 8 chunks
                uint32_t dst = sb + (uint32_t)p * PLA + (uint32_t)(r * (PITCH * 2) + c * 16);
                cp16(dst, pa[p] + (size_t)(m0 + r) * lda + k0 + c * 8);
            }
        }
#pragma unroll
        for (int p = 0; p < 2; p++) {
#pragma unroll
            for (int it = 0; it < 2; it++) {
                int id = tid + it * NT;                  // 1024 chunks
                int r = id >> 3, c = id & 7;             // 128 rows x 8 chunks
                uint32_t dst = sb + (uint32_t)(2 * PLA) + (uint32_t)p * PLB +
                               (uint32_t)(r * (PITCH * 2) + c * 16);
                cp16(dst, pb[p] + (size_t)(n0 + r) * ldb + k0 + c * 8);
            }
        }
    };

    wmma::fragment<wmma::accumulator, 16, 16, 16, float> acc[4][2];
#pragma unroll
    for (int i = 0; i < 4; i++)
#pragma unroll
        for (int j = 0; j < 2; j++) wmma::fill_fragment(acc[i][j], 0.f);

    // prologue
    load_stage(0); cp_commit();
    load_stage(1); cp_commit();

    for (int i = 0; i < niter; i++) {
        cp_wait1();          // stage i resident (stage i+1 may still be in flight)
        __syncthreads();

        // compute stage i (load of stage i+1 overlaps this)
        const __nv_bfloat16* As_hi = smem + (size_t)(i % STAGES) * (STAGEB / 2);
        const __nv_bfloat16* As_lo = As_hi + PLA / 2;
        const __nv_bfloat16* Bs_hi = As_hi + PLA;
        const __nv_bfloat16* Bs_lo = Bs_hi + PLB / 2;

#pragma unroll
        for (int kk = 0; kk < BK; kk += 16) {
            wmma::fragment<wmma::matrix_a, 16, 16, 16, __nv_bfloat16, wmma::row_major> ah[4], al[4];
#pragma unroll
            for (int x = 0; x < 4; x++) {
                int row = wm * 64 + x * 16;
                wmma::load_matrix_sync(ah[x], As_hi + row * PITCH + kk, PITCH);
                wmma::load_matrix_sync(al[x], As_lo + row * PITCH + kk, PITCH);
            }
#pragma unroll
            for (int y = 0; y < 2; y++) {
                int col = wn * 32 + y * 16;
                wmma::fragment<wmma::matrix_b, 16, 16, 16, __nv_bfloat16, wmma::col_major> bh, bl;
                wmma::load_matrix_sync(bh, Bs_hi + col * PITCH + kk, PITCH);
                wmma::load_matrix_sync(bl, Bs_lo + col * PITCH + kk, PITCH);
#pragma unroll
                for (int x = 0; x < 4; x++) {
                    wmma::mma_sync(acc[x][y], ah[x], bh, acc[x][y]);
                    wmma::mma_sync(acc[x][y], ah[x], bl, acc[x][y]);
                    wmma::mma_sync(acc[x][y], al[x], bh, acc[x][y]);
                }
            }
        }
        __syncthreads();     // compute done before overwriting this buffer

        // prefetch stage i+2 into the buffer just freed
        if (i + 2 < niter) load_stage(i + 2);
        cp_commit();         // (possibly empty) keeps wait_group accounting uniform
    }

    // ---------------- epilogue ----------------
    if (MODE == 0) {
        float* C = reinterpret_cast<float*>(C0) + (size_t)b * strC;
#pragma unroll
        for (int x = 0; x < 4; x++)
#pragma unroll
            for (int y = 0; y < 2; y++) {
                int gr = m0 + wm * 64 + x * 16;
                int gc = n0 + wn * 32 + y * 16;
                wmma::store_matrix_sync(C + (size_t)gr * ldc + gc, acc[x][y], ldc,
                                        wmma::mem_row_major);
            }
    } else {
        // per-warp 16x36 f32 staging slab (stage buffers dead after final barrier)
        float* stage = reinterpret_cast<float*>(smem) + wid * (16 * 36);
        int wr0 = m0 + wm * 64, wc0 = n0 + wn * 32;
#pragma unroll
        for (int x = 0; x < 4; x++) {
            wmma::store_matrix_sync(stage, acc[x][0], 36, wmma::mem_row_major);
            wmma::store_matrix_sync(stage + 16, acc[x][1], 36, wmma::mem_row_major);
            __syncwarp();
#pragma unroll
            for (int it = 0; it < 4; it++) {
                int idx = lane + it * 32;
                int r = idx >> 3, c = (idx & 7) << 2;
                float4 v = *reinterpret_cast<float4*>(stage + r * 36 + c);
                int gr = wr0 + x * 16 + r, gc = wc0 + c;
                if (MODE == 2) {
                    v.x += bias[gc]; v.y += bias[gc + 1];
                    v.z += bias[gc + 2]; v.w += bias[gc + 3];
                    float* C = reinterpret_cast<float*>(C0);
                    *reinterpret_cast<float4*>(C + (size_t)gr * ldc + gc) = v;
                } else {
                    __nv_bfloat16* Ch = reinterpret_cast<__nv_bfloat16*>(C0) + (size_t)b * strC;
                    __nv_bfloat16* Cl = reinterpret_cast<__nv_bfloat16*>(C1) + (size_t)b * strC;
                    float f[4] = {v.x, v.y, v.z, v.w};
                    __nv_bfloat16 h[4], l[4];
#pragma unroll
                    for (int q = 0; q < 4; q++) {
                        h[q] = __float2bfloat16(f[q]);
                        l[q] = __float2bfloat16(f[q] - __bfloat162float(h[q]));
                    }
                    size_t o = (size_t)gr * ldc + gc;
                    *reinterpret_cast<uint2*>(Ch + o) = *reinterpret_cast<const uint2*>(h);
                    *reinterpret_cast<uint2*>(Cl + o) = *reinterpret_cast<const uint2*>(l);
                }
            }
            __syncwarp();
        }
    }
}

// ================= launch =================
extern "C" void kernel_launch(void* const* d_in, const int* in_sizes, int n_in,
                              void* d_out, int out_size) {
    const float* Q    = (const float*)d_in[0];
    const float* Kx   = (const float*)d_in[1];
    const float* V    = (const float*)d_in[2];
    const float* mask = (const float*)d_in[3];
    const float* W    = (const float*)d_in[4];
    const float* bias = (const float*)d_in[5];
    const int*   inv  = (const int*)d_in[6];

    void *pQh, *pQl, *pKh, *pKl, *pVh, *pVl, *pWh, *pWl, *pS, *pPh, *pPl;
    cudaGetSymbolAddress(&pQh, g_Qhi);  cudaGetSymbolAddress(&pQl, g_Qlo);
    cudaGetSymbolAddress(&pKh, g_Khi);  cudaGetSymbolAddress(&pKl, g_Klo);
    cudaGetSymbolAddress(&pVh, g_Vthi); cudaGetSymbolAddress(&pVl, g_Vtlo);
    cudaGetSymbolAddress(&pWh, g_Whi);  cudaGetSymbolAddress(&pWl, g_Wlo);
    cudaGetSymbolAddress(&pS, g_scores);
    cudaGetSymbolAddress(&pPh, g_Phi);  cudaGetSymbolAddress(&pPl, g_Plo);

    __nv_bfloat16 *Qh = (__nv_bfloat16*)pQh, *Ql = (__nv_bfloat16*)pQl;
    __nv_bfloat16 *Kh = (__nv_bfloat16*)pKh, *Kl = (__nv_bfloat16*)pKl;
    __nv_bfloat16 *Vh = (__nv_bfloat16*)pVh, *Vl = (__nv_bfloat16*)pVl;
    __nv_bfloat16 *Wh = (__nv_bfloat16*)pWh, *Wl = (__nv_bfloat16*)pWl;
    float* Sc = (float*)pS;
    __nv_bfloat16 *Ph = (__nv_bfloat16*)pPh, *Pl = (__nv_bfloat16*)pPl;
    __nv_bfloat16 *Ath = Qh, *Atl = Ql;  // attn reuses Q planes

    cudaFuncSetAttribute(gemm_pipe<0>, cudaFuncAttributeMaxDynamicSharedMemorySize, GSMEM);
    cudaFuncSetAttribute(gemm_pipe<1>, cudaFuncAttributeMaxDynamicSharedMemorySize, GSMEM);
    cudaFuncSetAttribute(gemm_pipe<2>, cudaFuncAttributeMaxDynamicSharedMemorySize, GSMEM);

    // splits
    int n8 = B_ * S_ * E_ / 8;
    split_plane<<<(n8 + 255) / 256, 256>>>(Q, Qh, Ql, n8);
    split_plane<<<(n8 + 255) / 256, 256>>>(Kx, Kh, Kl, n8);
    int w8 = E_ * E_ / 8;
    split_plane<<<(w8 + 255) / 256, 256>>>(W, Wh, Wl, w8);
    dim3 gt(S_ / 32, E_ / 32, B_);
    splitT_v<<<gt, 256>>>(V, Vh, Vl);

    // GEMM1: scores = Q @ K^T  [M=S, N=S, K=E]
    dim3 g1(S_ / BN, S_ / BM, B_);
    gemm_pipe<0><<<g1, NT, GSMEM>>>(Qh, Ql, E_, (size_t)S_ * E_,
                                    Kh, Kl, E_, (size_t)S_ * E_,
                                    Sc, nullptr, S_, (size_t)S_ * S_, nullptr, E_);

    // softmax * mask -> planar probs
    softmax_mask_kernel<<<B_ * S_, 256>>>(Sc, mask, Ph, Pl, inv);

    // GEMM2: attn = P @ Vt^T   [M=S, N=E, K=S]
    dim3 g2(E_ / BN, S_ / BM, B_);
    gemm_pipe<1><<<g2, NT, GSMEM>>>(Ph, Pl, S_, (size_t)S_ * S_,
                                    Vh, Vl, S_, (size_t)E_ * S_,
                                    Ath, Atl, E_, (size_t)S_ * E_, nullptr, S_);

    // GEMM3: out = attn @ W^T + bias  [M=B*S, N=E, K=E]
    dim3 g3(E_ / BN, (B_ * S_) / BM, 1);
    gemm_pipe<2><<<g3, NT, GSMEM>>>(Ath, Atl, E_, 0,
                                    Wh, Wl, E_, 0,
                                    d_out, nullptr, E_, 0, bias, E_);
}

// round 8
// speedup vs baseline: 1.1399x; 1.1192x over previous
#include <cuda_runtime.h>
#include <cuda_bf16.h>
#include <cstdint>
#include <cstddef>
#include <mma.h>

using namespace nvcuda;

#define B_ 8
#define S_ 2048
#define E_ 1024

// ================= scratch (device globals; allocation-free rule) =================
__device__ __nv_bfloat16 g_Qhi[(size_t)B_ * S_ * E_];
__device__ __nv_bfloat16 g_Qlo[(size_t)B_ * S_ * E_];
__device__ __nv_bfloat16 g_Khi[(size_t)B_ * S_ * E_];
__device__ __nv_bfloat16 g_Klo[(size_t)B_ * S_ * E_];
__device__ __nv_bfloat16 g_Vthi[(size_t)B_ * E_ * S_];  // V transposed: [B, E, S]
__device__ __nv_bfloat16 g_Vtlo[(size_t)B_ * E_ * S_];
__device__ __nv_bfloat16 g_Whi[(size_t)E_ * E_];
__device__ __nv_bfloat16 g_Wlo[(size_t)E_ * E_];
__device__ float         g_scores[(size_t)B_ * S_ * S_];
__device__ __nv_bfloat16 g_Phi[(size_t)B_ * S_ * S_];
__device__ __nv_bfloat16 g_Plo[(size_t)B_ * S_ * S_];
// attn split reuses g_Qhi/g_Qlo (Q dead after GEMM1)

// ================= async-copy helpers =================
__device__ __forceinline__ uint32_t smem_u32(const void* p) {
    uint32_t a;
    asm("{ .reg .u64 t; cvta.to.shared.u64 t, %1; cvt.u32.u64 %0, t; }" : "=r"(a) : "l"(p));
    return a;
}
__device__ __forceinline__ void cp16(uint32_t dst, const void* src) {
    asm volatile("cp.async.cg.shared.global [%0], [%1], 16;" :: "r"(dst), "l"(src) : "memory");
}
__device__ __forceinline__ void cp_commit() { asm volatile("cp.async.commit_group;" ::: "memory"); }
__device__ __forceinline__ void cp_wait1()  { asm volatile("cp.async.wait_group 1;" ::: "memory"); }

// ================= split kernels =================
__global__ void __launch_bounds__(256) split_plane(const float* __restrict__ x,
                                                   __nv_bfloat16* __restrict__ hi,
                                                   __nv_bfloat16* __restrict__ lo, int n8) {
    int i = blockIdx.x * blockDim.x + threadIdx.x;
    if (i >= n8) return;
    const float4* x4 = reinterpret_cast<const float4*>(x) + (size_t)i * 2;
    float4 a = x4[0], b = x4[1];
    float f[8] = {a.x, a.y, a.z, a.w, b.x, b.y, b.z, b.w};
    __nv_bfloat16 h[8], l[8];
#pragma unroll
    for (int j = 0; j < 8; j++) {
        h[j] = __float2bfloat16(f[j]);
        l[j] = __float2bfloat16(f[j] - __bfloat162float(h[j]));
    }
    *reinterpret_cast<uint4*>(hi + (size_t)i * 8) = *reinterpret_cast<const uint4*>(h);
    *reinterpret_cast<uint4*>(lo + (size_t)i * 8) = *reinterpret_cast<const uint4*>(l);
}

// V [B,S,E] f32 -> transposed planes [B,E,S] bf16 hi/lo
__global__ void __launch_bounds__(256) splitT_v(const float* __restrict__ v,
                                                __nv_bfloat16* __restrict__ hi,
                                                __nv_bfloat16* __restrict__ lo) {
    __shared__ float tile[32][33];
    int b = blockIdx.z;
    int s0 = blockIdx.x * 32, e0 = blockIdx.y * 32;
    int tx = threadIdx.x & 31, ty = threadIdx.x >> 5;
    const float* vb = v + (size_t)b * S_ * E_;
#pragma unroll
    for (int k = 0; k < 4; k++)
        tile[ty + 8 * k][tx] = vb[(size_t)(s0 + ty + 8 * k) * E_ + e0 + tx];
    __syncthreads();
    __nv_bfloat16* hb = hi + (size_t)b * E_ * S_;
    __nv_bfloat16* lb = lo + (size_t)b * E_ * S_;
#pragma unroll
    for (int k = 0; k < 4; k++) {
        float f = tile[tx][ty + 8 * k];
        __nv_bfloat16 h = __float2bfloat16(f);
        size_t o = (size_t)(e0 + ty + 8 * k) * S_ + s0 + tx;
        hb[o] = h;
        lb[o] = __float2bfloat16(f - __bfloat162float(h));
    }
}

// ================= softmax * mask -> planar bf16 hi/lo probs (vectorized) ========
__global__ void __launch_bounds__(256) softmax_mask_kernel(
    const float* __restrict__ scores, const float* __restrict__ mask,
    __nv_bfloat16* __restrict__ phi, __nv_bfloat16* __restrict__ plo,
    const int* __restrict__ sc) {
    __shared__ float redmax[8], redsum[8];
    size_t row = blockIdx.x;
    const float4* srow = reinterpret_cast<const float4*>(scores + row * (size_t)S_);
    const float4* mrow = reinterpret_cast<const float4*>(mask + row * (size_t)S_);
    int t = threadIdx.x, lane = t & 31, warp = t >> 5;

    int iv = *sc;
    float denom = (iv == 32) ? 32.0f : __int_as_float(iv);
    float scale = 1.0f / denom;

    // 2 float4 per thread: elements 4*(t + 256*j) .. +3
    float v[8];
#pragma unroll
    for (int j = 0; j < 2; j++) {
        float4 x = srow[t + 256 * j];
        v[4 * j + 0] = x.x * scale; v[4 * j + 1] = x.y * scale;
        v[4 * j + 2] = x.z * scale; v[4 * j + 3] = x.w * scale;
    }
    float m = v[0];
#pragma unroll
    for (int j = 1; j < 8; j++) m = fmaxf(m, v[j]);
#pragma unroll
    for (int o = 16; o; o >>= 1) m = fmaxf(m, __shfl_xor_sync(0xffffffffu, m, o));
    if (lane == 0) redmax[warp] = m;
    __syncthreads();
    float bm = redmax[0];
#pragma unroll
    for (int w = 1; w < 8; w++) bm = fmaxf(bm, redmax[w]);
    float e[8], s = 0.f;
#pragma unroll
    for (int j = 0; j < 8; j++) { e[j] = __expf(v[j] - bm); s += e[j]; }
#pragma unroll
    for (int o = 16; o; o >>= 1) s += __shfl_xor_sync(0xffffffffu, s, o);
    if (lane == 0) redsum[warp] = s;
    __syncthreads();
    float bs = 0.f;
#pragma unroll
    for (int w = 0; w < 8; w++) bs += redsum[w];
    float inv = 1.0f / bs;

    __nv_bfloat16* ph = phi + row * (size_t)S_;
    __nv_bfloat16* pl = plo + row * (size_t)S_;
#pragma unroll
    for (int j = 0; j < 2; j++) {
        float4 mk = mrow[t + 256 * j];
        float mf[4] = {mk.x, mk.y, mk.z, mk.w};
        __nv_bfloat16 h[4], l[4];
#pragma unroll
        for (int q = 0; q < 4; q++) {
            float p = e[4 * j + q] * inv * mf[q];
            h[q] = __float2bfloat16(p);
            l[q] = __float2bfloat16(p - __bfloat162float(h[q]));
        }
        int o = 4 * (t + 256 * j);
        *reinterpret_cast<uint2*>(ph + o) = *reinterpret_cast<const uint2*>(h);
        *reinterpret_cast<uint2*>(pl + o) = *reinterpret_cast<const uint2*>(l);
    }
}

// ================= pipelined split-bf16 WMMA NT GEMM (R5 shape) =================
// C[M,N] = sum_k A[m,k]*B[n,k]; A/B planar hi/lo bf16, fp32 accum via HMMA.
// MODE 0: f32 out. MODE 1: planar bf16 hi/lo out. MODE 2: f32 + bias out.
constexpr int BM = 128, BN = 128, BK = 64;
constexpr int PITCH = 72;                       // BK + 8 pad (bf16 elems)
constexpr int PLANEB = BM * PITCH * 2;          // 18432 B per plane tile
constexpr int STAGEB = 4 * PLANEB;              // Ahi/Alo/Bhi/Blo = 73728 B
constexpr int STAGES = 3;
constexpr unsigned GSMEM = STAGES * STAGEB;     // 221184 B

template <int MODE>
__global__ void __launch_bounds__(256) gemm_pipe(
    const __nv_bfloat16* __restrict__ Ahi, const __nv_bfloat16* __restrict__ Alo,
    int lda, size_t strA,
    const __nv_bfloat16* __restrict__ Bhi, const __nv_bfloat16* __restrict__ Blo,
    int ldb, size_t strB,
    void* __restrict__ C0, void* __restrict__ C1, int ldc, size_t strC,
    const float* __restrict__ bias, int Kdim) {
    extern __shared__ __nv_bfloat16 smem[];
    const uint32_t sbase = smem_u32(smem);
    const int tid = threadIdx.x;
    const int lane = tid & 31, wid = tid >> 5;
    const int wm = wid >> 1;                 // 0..3  (32-row strips)
    const int wn = wid & 1;                  // 0..1  (64-col strips)
    const int b = blockIdx.z;
    const int m0 = blockIdx.y * BM, n0 = blockIdx.x * BN;

    const __nv_bfloat16* pa[2] = {Ahi + (size_t)b * strA, Alo + (size_t)b * strA};
    const __nv_bfloat16* pb[2] = {Bhi + (size_t)b * strB, Blo + (size_t)b * strB};

    const int niter = Kdim / BK;

    // stage loader: 4 planes x (128 rows x 64 bf16) with cp.async 16B chunks
    auto load_stage = [&](int j) {
        const int k0 = j * BK;
        const uint32_t sb = sbase + (j % STAGES) * STAGEB;
#pragma unroll
        for (int p = 0; p < 4; p++) {
            const __nv_bfloat16* src = (p < 2) ? pa[p] : pb[p - 2];
            const int r0 = (p < 2) ? m0 : n0;
            const int ld = (p < 2) ? lda : ldb;
#pragma unroll
            for (int it = 0; it < 4; it++) {
                int id = tid + it * 256;          // 1024 chunks
                int r = id >> 3, c = id & 7;      // 128 rows x 8 x 16B
                uint32_t dst = sb + (uint32_t)p * PLANEB + (uint32_t)(r * PITCH * 2 + c * 16);
                cp16(dst, src + (size_t)(r0 + r) * ld + k0 + c * 8);
            }
        }
    };

    wmma::fragment<wmma::accumulator, 16, 16, 16, float> acc[2][4];
#pragma unroll
    for (int i = 0; i < 2; i++)
#pragma unroll
        for (int j = 0; j < 4; j++) wmma::fill_fragment(acc[i][j], 0.f);

    // prologue
    load_stage(0); cp_commit();
    load_stage(1); cp_commit();

    for (int i = 0; i < niter; i++) {
        cp_wait1();          // stage i resident (only stage i+1 may still be in flight)
        __syncthreads();

        // prefetch stage i+2 (overwrites buffer of stage i-1; safe past the barrier)
        if (i + 2 < niter) load_stage(i + 2);
        cp_commit();

        // compute stage i
        const __nv_bfloat16* As_hi =
            smem + (size_t)(i % STAGES) * (STAGEB / 2);
        const __nv_bfloat16* As_lo = As_hi + PLANEB / 2;
        const __nv_bfloat16* Bs_hi = As_hi + 2 * (PLANEB / 2);
        const __nv_bfloat16* Bs_lo = As_hi + 3 * (PLANEB / 2);

#pragma unroll
        for (int kk = 0; kk < BK; kk += 16) {
            // ---- load all fragments first ----
            wmma::fragment<wmma::matrix_a, 16, 16, 16, __nv_bfloat16, wmma::row_major> ah[2], al[2];
#pragma unroll
            for (int x = 0; x < 2; x++) {
                int row = wm * 32 + x * 16;
                wmma::load_matrix_sync(ah[x], As_hi + row * PITCH + kk, PITCH);
                wmma::load_matrix_sync(al[x], As_lo + row * PITCH + kk, PITCH);
            }
            wmma::fragment<wmma::matrix_b, 16, 16, 16, __nv_bfloat16, wmma::col_major> bh[4], bl[4];
#pragma unroll
            for (int y = 0; y < 4; y++) {
                int col = wn * 64 + y * 16;
                wmma::load_matrix_sync(bh[y], Bs_hi + col * PITCH + kk, PITCH);
                wmma::load_matrix_sync(bl[y], Bs_lo + col * PITCH + kk, PITCH);
            }
            // ---- phase-ordered issue: 8 independent MMAs per phase ----
#pragma unroll
            for (int x = 0; x < 2; x++)
#pragma unroll
                for (int y = 0; y < 4; y++)
                    wmma::mma_sync(acc[x][y], ah[x], bh[y], acc[x][y]);
#pragma unroll
            for (int x = 0; x < 2; x++)
#pragma unroll
                for (int y = 0; y < 4; y++)
                    wmma::mma_sync(acc[x][y], ah[x], bl[y], acc[x][y]);
#pragma unroll
            for (int x = 0; x < 2; x++)
#pragma unroll
                for (int y = 0; y < 4; y++)
                    wmma::mma_sync(acc[x][y], al[x], bh[y], acc[x][y]);
        }
        __syncthreads();
    }

    // ---------------- epilogue ----------------
    if (MODE == 0) {
        float* C = reinterpret_cast<float*>(C0) + (size_t)b * strC;
#pragma unroll
        for (int x = 0; x < 2; x++)
#pragma unroll
            for (int y = 0; y < 4; y++) {
                int gr = m0 + wm * 32 + x * 16;
                int gc = n0 + wn * 64 + y * 16;
                wmma::store_matrix_sync(C + (size_t)gr * ldc + gc, acc[x][y], ldc,
                                        wmma::mem_row_major);
            }
    } else {
        // stage accumulators through smem for coalesced stores (stage buffers dead)
        float* stage = reinterpret_cast<float*>(smem) + wid * (32 * 72);
#pragma unroll
        for (int x = 0; x < 2; x++)
#pragma unroll
            for (int y = 0; y < 4; y++)
                wmma::store_matrix_sync(stage + x * 16 * 72 + y * 16, acc[x][y], 72,
                                        wmma::mem_row_major);
        __syncwarp();
        int wr0 = m0 + wm * 32, wc0 = n0 + wn * 64;
#pragma unroll
        for (int it = 0; it < 16; it++) {
            int idx = lane + it * 32;
            int r = idx >> 4, c = (idx & 15) << 2;
            float4 v = *reinterpret_cast<float4*>(stage + r * 72 + c);
            int gr = wr0 + r, gc = wc0 + c;
            if (MODE == 2) {
                v.x += bias[gc]; v.y += bias[gc + 1]; v.z += bias[gc + 2]; v.w += bias[gc + 3];
                float* C = reinterpret_cast<float*>(C0);
                *reinterpret_cast<float4*>(C + (size_t)gr * ldc + gc) = v;
            } else {
                __nv_bfloat16* Ch = reinterpret_cast<__nv_bfloat16*>(C0) + (size_t)b * strC;
                __nv_bfloat16* Cl = reinterpret_cast<__nv_bfloat16*>(C1) + (size_t)b * strC;
                float f[4] = {v.x, v.y, v.z, v.w};
                __nv_bfloat16 h[4], l[4];
#pragma unroll
                for (int q = 0; q < 4; q++) {
                    h[q] = __float2bfloat16(f[q]);
                    l[q] = __float2bfloat16(f[q] - __bfloat162float(h[q]));
                }
                size_t o = (size_t)gr * ldc + gc;
                *reinterpret_cast<uint2*>(Ch + o) = *reinterpret_cast<const uint2*>(h);
                *reinterpret_cast<uint2*>(Cl + o) = *reinterpret_cast<const uint2*>(l);
            }
        }
    }
}

// ================= launch =================
extern "C" void kernel_launch(void* const* d_in, const int* in_sizes, int n_in,
                              void* d_out, int out_size) {
    const float* Q    = (const float*)d_in[0];
    const float* Kx   = (const float*)d_in[1];
    const float* V    = (const float*)d_in[2];
    const float* mask = (const float*)d_in[3];
    const float* W    = (const float*)d_in[4];
    const float* bias = (const float*)d_in[5];
    const int*   inv  = (const int*)d_in[6];

    void *pQh, *pQl, *pKh, *pKl, *pVh, *pVl, *pWh, *pWl, *pS, *pPh, *pPl;
    cudaGetSymbolAddress(&pQh, g_Qhi);  cudaGetSymbolAddress(&pQl, g_Qlo);
    cudaGetSymbolAddress(&pKh, g_Khi);  cudaGetSymbolAddress(&pKl, g_Klo);
    cudaGetSymbolAddress(&pVh, g_Vthi); cudaGetSymbolAddress(&pVl, g_Vtlo);
    cudaGetSymbolAddress(&pWh, g_Whi);  cudaGetSymbolAddress(&pWl, g_Wlo);
    cudaGetSymbolAddress(&pS, g_scores);
    cudaGetSymbolAddress(&pPh, g_Phi);  cudaGetSymbolAddress(&pPl, g_Plo);

    __nv_bfloat16 *Qh = (__nv_bfloat16*)pQh, *Ql = (__nv_bfloat16*)pQl;
    __nv_bfloat16 *Kh = (__nv_bfloat16*)pKh, *Kl = (__nv_bfloat16*)pKl;
    __nv_bfloat16 *Vh = (__nv_bfloat16*)pVh, *Vl = (__nv_bfloat16*)pVl;
    __nv_bfloat16 *Wh = (__nv_bfloat16*)pWh, *Wl = (__nv_bfloat16*)pWl;
    float* Sc = (float*)pS;
    __nv_bfloat16 *Ph = (__nv_bfloat16*)pPh, *Pl = (__nv_bfloat16*)pPl;
    __nv_bfloat16 *Ath = Qh, *Atl = Ql;  // attn reuses Q planes

    cudaFuncSetAttribute(gemm_pipe<0>, cudaFuncAttributeMaxDynamicSharedMemorySize, GSMEM);
    cudaFuncSetAttribute(gemm_pipe<1>, cudaFuncAttributeMaxDynamicSharedMemorySize, GSMEM);
    cudaFuncSetAttribute(gemm_pipe<2>, cudaFuncAttributeMaxDynamicSharedMemorySize, GSMEM);

    // splits
    int n8 = B_ * S_ * E_ / 8;
    split_plane<<<(n8 + 255) / 256, 256>>>(Q, Qh, Ql, n8);
    split_plane<<<(n8 + 255) / 256, 256>>>(Kx, Kh, Kl, n8);
    int w8 = E_ * E_ / 8;
    split_plane<<<(w8 + 255) / 256, 256>>>(W, Wh, Wl, w8);
    dim3 gt(S_ / 32, E_ / 32, B_);
    splitT_v<<<gt, 256>>>(V, Vh, Vl);

    // GEMM1: scores = Q @ K^T  [M=S, N=S, K=E]
    dim3 g1(S_ / BN, S_ / BM, B_);
    gemm_pipe<0><<<g1, 256, GSMEM>>>(Qh, Ql, E_, (size_t)S_ * E_,
                                     Kh, Kl, E_, (size_t)S_ * E_,
                                     Sc, nullptr, S_, (size_t)S_ * S_, nullptr, E_);

    // softmax * mask -> planar probs
    softmax_mask_kernel<<<B_ * S_, 256>>>(Sc, mask, Ph, Pl, inv);

    // GEMM2: attn = P @ Vt^T   [M=S, N=E, K=S]
    dim3 g2(E_ / BN, S_ / BM, B_);
    gemm_pipe<1><<<g2, 256, GSMEM>>>(Ph, Pl, S_, (size_t)S_ * S_,
                                     Vh, Vl, S_, (size_t)E_ * S_,
                                     Ath, Atl, E_, (size_t)S_ * E_, nullptr, S_);

    // GEMM3: out = attn @ W^T + bias  [M=B*S, N=E, K=E]
    dim3 g3(E_ / BN, (B_ * S_) / BM, 1);
    gemm_pipe<2><<<g3, 256, GSMEM>>>(Ath, Atl, E_, 0,
                                     Wh, Wl, E_, 0,
                                     d_out, nullptr, E_, 0, bias, E_);
}